// round 1
// baseline (speedup 1.0000x reference)
#include <cuda_runtime.h>
#include <cstddef>

// HaarDown: x (B=8, C=64, H=512, W=512) f32 -> out (B, C*3, H2=256, W2=256) f32
// For each 2x2 block [a b; c d]:
//   o0 = (a - b - c + d) * 0.5
//   o1 = (a - b + c - d) * 0.5
//   o2 = (a + b - c - d) * 0.5
// out channel layout: channel index = c*3 + k   (stack axis=2 then reshape)

namespace {
constexpr int B  = 8;
constexpr int C  = 64;
constexpr int H  = 512;
constexpr int W  = 512;
constexpr int H2 = H / 2;   // 256
constexpr int W2 = W / 2;   // 256
constexpr int WG = W2 / 4;  // 64 groups of 4 output columns per row
// total threads = (B*C) * H2 * WG = 512 * 256 * 64 = 8,388,608
constexpr int THREADS_PER_BLOCK = 256;
constexpr long long TOTAL_THREADS = (long long)B * C * H2 * WG;
constexpr int NUM_BLOCKS = (int)(TOTAL_THREADS / THREADS_PER_BLOCK); // 32768
}

__global__ __launch_bounds__(THREADS_PER_BLOCK)
void haar_down_kernel(const float* __restrict__ x, float* __restrict__ out) {
    int tid = blockIdx.x * THREADS_PER_BLOCK + threadIdx.x;

    int wg = tid % WG;                 // group of 4 output columns
    int h2 = (tid / WG) % H2;          // output row
    int bc = tid / (WG * H2);          // fused (b, c): 0..511

    // Input: two rows of 8 consecutive floats (covers 4 output columns)
    const float* p0 = x + (size_t)bc * (H * W) + (size_t)(2 * h2) * W + wg * 8;
    const float4 r0a = __ldg((const float4*)(p0));
    const float4 r0b = __ldg((const float4*)(p0 + 4));
    const float4 r1a = __ldg((const float4*)(p0 + W));
    const float4 r1b = __ldg((const float4*)(p0 + W + 4));

    float4 o0, o1, o2;

    // column 0: a=r0a.x b=r0a.y c=r1a.x d=r1a.y
    {
        float amb = r0a.x - r0a.y;     // a - b
        float apb = r0a.x + r0a.y;     // a + b
        float cmd = r1a.x - r1a.y;     // c - d
        float cpd = r1a.x + r1a.y;     // c + d
        o0.x = (amb - cmd) * 0.5f;     // a-b-c+d
        o1.x = (amb + cmd) * 0.5f;     // a-b+c-d
        o2.x = (apb - cpd) * 0.5f;     // a+b-c-d
    }
    // column 1: a=r0a.z b=r0a.w c=r1a.z d=r1a.w
    {
        float amb = r0a.z - r0a.w;
        float apb = r0a.z + r0a.w;
        float cmd = r1a.z - r1a.w;
        float cpd = r1a.z + r1a.w;
        o0.y = (amb - cmd) * 0.5f;
        o1.y = (amb + cmd) * 0.5f;
        o2.y = (apb - cpd) * 0.5f;
    }
    // column 2: a=r0b.x b=r0b.y c=r1b.x d=r1b.y
    {
        float amb = r0b.x - r0b.y;
        float apb = r0b.x + r0b.y;
        float cmd = r1b.x - r1b.y;
        float cpd = r1b.x + r1b.y;
        o0.z = (amb - cmd) * 0.5f;
        o1.z = (amb + cmd) * 0.5f;
        o2.z = (apb - cpd) * 0.5f;
    }
    // column 3: a=r0b.z b=r0b.w c=r1b.z d=r1b.w
    {
        float amb = r0b.z - r0b.w;
        float apb = r0b.z + r0b.w;
        float cmd = r1b.z - r1b.w;
        float cpd = r1b.z + r1b.w;
        o0.w = (amb - cmd) * 0.5f;
        o1.w = (amb + cmd) * 0.5f;
        o2.w = (apb - cpd) * 0.5f;
    }

    // Output: channel = c*3 + k, where bc = b*C + c
    int b = bc >> 6;          // / 64
    int c = bc & 63;          // % 64
    constexpr int PLANE = H2 * W2; // 65536
    float* obase = out + ((size_t)(b * (C * 3) + c * 3) * PLANE)
                       + (size_t)h2 * W2 + wg * 4;

    *((float4*)(obase))             = o0;
    *((float4*)(obase + PLANE))     = o1;
    *((float4*)(obase + 2 * PLANE)) = o2;
}

extern "C" void kernel_launch(void* const* d_in, const int* in_sizes, int n_in,
                              void* d_out, int out_size) {
    const float* x = (const float*)d_in[0];
    float* out = (float*)d_out;
    haar_down_kernel<<<NUM_BLOCKS, THREADS_PER_BLOCK>>>(x, out);
}

// round 2
// speedup vs baseline: 1.0005x; 1.0005x over previous
#include <cuda_runtime.h>
#include <cstddef>

// HaarDown: x (B=8, C=64, H=512, W=512) f32 -> out (B, C*3, H2=256, W2=256) f32
// 2x2 block [a b; c d]:
//   o0 = (a - b - c + d) * 0.5
//   o1 = (a - b + c - d) * 0.5
//   o2 = (a + b - c - d) * 0.5
// out channel = c*3 + k
//
// Pure HBM-streaming kernel. Uses sm_103a 256-bit vector ld/st:
//   - ld.global.nc.v8.f32 (L1-nc, 32B per lane -> one 128B line per 4 lanes)
//   - st.global.cs.v8.f32 (evict-first; zero reuse)
// Each thread: 2 rows x 16 floats input (128B), 3 x 8 floats output (96B).

namespace {
constexpr int B  = 8;
constexpr int C  = 64;
constexpr int H  = 512;
constexpr int W  = 512;
constexpr int H2 = H / 2;   // 256
constexpr int W2 = W / 2;   // 256
constexpr int WG = W2 / 8;  // 32 groups of 8 output columns per row
constexpr int THREADS_PER_BLOCK = 256;
constexpr long long TOTAL_THREADS = (long long)B * C * H2 * WG; // 4,194,304
constexpr int NUM_BLOCKS = (int)(TOTAL_THREADS / THREADS_PER_BLOCK); // 16384
}

__device__ __forceinline__ void ldg256_nc(const float* p, float v[8]) {
    asm volatile(
        "ld.global.nc.v8.f32 {%0,%1,%2,%3,%4,%5,%6,%7}, [%8];"
        : "=f"(v[0]), "=f"(v[1]), "=f"(v[2]), "=f"(v[3]),
          "=f"(v[4]), "=f"(v[5]), "=f"(v[6]), "=f"(v[7])
        : "l"(p));
}

__device__ __forceinline__ void stg256_cs(float* p, const float v[8]) {
    asm volatile(
        "st.global.cs.v8.f32 [%0], {%1,%2,%3,%4,%5,%6,%7,%8};"
        :: "l"(p),
           "f"(v[0]), "f"(v[1]), "f"(v[2]), "f"(v[3]),
           "f"(v[4]), "f"(v[5]), "f"(v[6]), "f"(v[7])
        : "memory");
}

__global__ __launch_bounds__(THREADS_PER_BLOCK)
void haar_down_kernel(const float* __restrict__ x, float* __restrict__ out) {
    int tid = blockIdx.x * THREADS_PER_BLOCK + threadIdx.x;

    int wg = tid % WG;                 // group of 8 output columns
    int h2 = (tid / WG) % H2;          // output row
    int bc = tid / (WG * H2);          // fused (b, c): 0..511

    // Input: two rows of 16 consecutive floats (covers 8 output columns).
    // Front-batch all 4 independent 256-bit loads (MLP=4, 128B).
    const float* p0 = x + (size_t)bc * (H * W) + (size_t)(2 * h2) * W + wg * 16;
    float r0[16], r1[16];
    ldg256_nc(p0,          r0);
    ldg256_nc(p0 + 8,      r0 + 8);
    ldg256_nc(p0 + W,      r1);
    ldg256_nc(p0 + W + 8,  r1 + 8);

    float o0[8], o1[8], o2[8];
    #pragma unroll
    for (int j = 0; j < 8; j++) {
        float a = r0[2 * j], b = r0[2 * j + 1];
        float c = r1[2 * j], d = r1[2 * j + 1];
        float amb = a - b;
        float apb = a + b;
        float cmd = c - d;
        float cpd = c + d;
        o0[j] = (amb - cmd) * 0.5f;   // a-b-c+d
        o1[j] = (amb + cmd) * 0.5f;   // a-b+c-d
        o2[j] = (apb - cpd) * 0.5f;   // a+b-c-d
    }

    // Output: channel = c*3 + k, bc = b*C + c
    int b = bc >> 6;          // / 64
    int c = bc & 63;          // % 64
    constexpr int PLANE = H2 * W2; // 65536
    float* obase = out + ((size_t)(b * (C * 3) + c * 3) * PLANE)
                       + (size_t)h2 * W2 + wg * 8;

    stg256_cs(obase,             o0);
    stg256_cs(obase + PLANE,     o1);
    stg256_cs(obase + 2 * PLANE, o2);
}

extern "C" void kernel_launch(void* const* d_in, const int* in_sizes, int n_in,
                              void* d_out, int out_size) {
    const float* x = (const float*)d_in[0];
    float* out = (float*)d_out;
    haar_down_kernel<<<NUM_BLOCKS, THREADS_PER_BLOCK>>>(x, out);
}